// round 16
// baseline (speedup 1.0000x reference)
#include <cuda_runtime.h>
#include <cuda_bf16.h>
#include <cuda_fp16.h>
#include <cstdint>

#define D      128
#define MAXN   50000
#define MAXE   850000
#define NG     512
#define SCHUNK 512
#define SBLK   ((MAXN + SCHUNK - 1) / SCHUNK)   // 98
#define PAD    136                               // smem row stride in bf16 elems
#define CAPW   64                                // per-warp edge cache

// ---- dynamic smem layout for MMA GEMM (bytes) ----
#define OFF_AS   0
#define OFF_AD   512
#define OFF_AHI  1024
#define TILE_B   (128 * PAD * 2)                 // 34816
#define OFF_ALO  (OFF_AHI + TILE_B)
#define OFF_WHI  (OFF_ALO + TILE_B)
#define OFF_WLO  (OFF_WHI + TILE_B)
#define GEMM_SMEM (OFF_WLO + TILE_B)             // 140288 bytes

// ---- fused setup job split (blocks of 256 threads) ----
#define NB_EMBED ((MAXN * (D / 4) + 255) / 256)  // 6250
#define NB_HIST  ((MAXE + 255) / 256)            // 3321 (covers any E0 <= MAXE)
#define NB_PREPW ((128 * 64 + 255) / 256)        // 32
#define NB_GOFF  3                               // 768 threads >= NG+1 = 513 entries
#define NB_SETUP (NB_EMBED + NB_HIST + 3 * NB_PREPW + NB_GOFF)

// ---------------- scratch (device globals; no allocation) ----------------
__device__ __half g_x[MAXN * D];                 // fp16 activations (layer inputs)
__device__ __half g_y[MAXN * D];
__device__ __half g_hh[MAXN * D];                // h in fp16 for the edge gather
__device__ float  g_as[MAXN];
__device__ float  g_ad[MAXN];
__device__ int    g_deg[MAXN];                   // zeroed at load; re-zeroed by k_scan3
__device__ int    g_rowptr[MAXN + 1];
__device__ int    g_cursor[MAXN];
__device__ int    g_csrc[MAXE];
__device__ int    g_goff[NG + 1];
__device__ int    g_part[SBLK];
// per-layer W images: [n][k] bf16, padded stride PAD, hi then lo (34816 B each)
__device__ uint4  g_wb[3][2 * TILE_B / 16];

// ---------------- PTX helpers ----------------
__device__ __forceinline__ uint32_t smem_u32(const void* p) {
    uint32_t a;
    asm("{ .reg .u64 t; cvta.to.shared.u64 t, %1; cvt.u32.u64 %0, t; }" : "=r"(a) : "l"(p));
    return a;
}
__device__ __forceinline__ void ldsm4(uint32_t& r0, uint32_t& r1, uint32_t& r2, uint32_t& r3,
                                      uint32_t addr) {
    asm volatile("ldmatrix.sync.aligned.m8n8.x4.shared.b16 {%0,%1,%2,%3}, [%4];"
                 : "=r"(r0), "=r"(r1), "=r"(r2), "=r"(r3) : "r"(addr));
}
__device__ __forceinline__ void mma16816(float& c0, float& c1, float& c2, float& c3,
                                         uint32_t a0, uint32_t a1, uint32_t a2, uint32_t a3,
                                         uint32_t b0, uint32_t b1) {
    asm volatile(
        "mma.sync.aligned.m16n8k16.row.col.f32.bf16.bf16.f32 "
        "{%0,%1,%2,%3}, {%4,%5,%6,%7}, {%8,%9}, {%0,%1,%2,%3};"
        : "+f"(c0), "+f"(c1), "+f"(c2), "+f"(c3)
        : "r"(a0), "r"(a1), "r"(a2), "r"(a3), "r"(b0), "r"(b1));
}

// ---------------- fused setup: embed | hist | prepw x3 | goff ----------------
__device__ __forceinline__ void do_prepw(int w, const float* __restrict__ W, int i) {
    if (i >= 128 * 64) return;
    int n  = i >> 6;
    int k2 = (i & 63) << 1;
    float v0 = W[k2 * D + n];
    float v1 = W[(k2 + 1) * D + n];
    __nv_bfloat16 h0 = __float2bfloat16(v0), h1 = __float2bfloat16(v1);
    __nv_bfloat16 l0 = __float2bfloat16(v0 - __bfloat162float(h0));
    __nv_bfloat16 l1 = __float2bfloat16(v1 - __bfloat162float(h1));
    __nv_bfloat162 hp, lp;
    hp.x = h0; hp.y = h1; lp.x = l0; lp.y = l1;
    char* base = (char*)g_wb[w];
    uint32_t off = (uint32_t)(n * PAD + k2) * 2;
    *(uint32_t*)(base + off)          = *(uint32_t*)&hp;
    *(uint32_t*)(base + TILE_B + off) = *(uint32_t*)&lp;
}

__global__ void k_setup(const int* __restrict__ ids, const float4* __restrict__ emb,
                        const int* __restrict__ batch, const int* __restrict__ dst, int E0,
                        const float* __restrict__ W1, const float* __restrict__ W2,
                        const float* __restrict__ W3, int N) {
    const int b = blockIdx.x, t = threadIdx.x;
    if (b < NB_EMBED) {                                   // embedding gather -> fp16 x
        int i = b * 256 + t;
        if (i < N * (D / 4)) {
            int node = i >> 5;
            int c    = i & 31;
            float4 v = emb[ids[node] * (D / 4) + c];
            uint2 pk;
            *(__half2*)&pk.x = __floats2half2_rn(v.x, v.y);
            *(__half2*)&pk.y = __floats2half2_rn(v.z, v.w);
            ((uint2*)g_x)[i] = pk;
        }
        return;
    }
    int b1 = b - NB_EMBED;
    if (b1 < NB_HIST) {                                   // degree histogram (deg starts 0)
        int i = b1 * 256 + t;
        if (i < E0) atomicAdd(&g_deg[dst[i]], 1);
        return;
    }
    b1 -= NB_HIST;
    if (b1 < 3 * NB_PREPW) {                              // W split/pack
        int w = b1 / NB_PREPW;
        int i = (b1 - w * NB_PREPW) * 256 + t;
        do_prepw(w, w == 0 ? W1 : (w == 1 ? W2 : W3), i);
        return;
    }
    b1 -= 3 * NB_PREPW;
    {                                                     // goff: lower_bound(batch, g), g in [0, NG]
        int g = b1 * 256 + t;
        if (g > NG) return;
        int lo = 0, hi = N;
        while (lo < hi) {
            int mid = (lo + hi) >> 1;
            if (batch[mid] < g) lo = mid + 1; else hi = mid;
        }
        g_goff[g] = lo;
    }
}

// ---------------- CSR scan (deg+1 accounts for the self-loop) ----------------
__global__ void k_scan1(int N) {
    __shared__ int red[8];
    int b = blockIdx.x, t = threadIdx.x;
    int base = b * SCHUNK;
    int s = 0;
    int i0 = base + t, i1 = base + t + 256;
    if (i0 < N) s += g_deg[i0] + 1;
    if (i1 < N) s += g_deg[i1] + 1;
    int lane = t & 31, wid = t >> 5;
    for (int o = 16; o; o >>= 1) s += __shfl_xor_sync(0xffffffffu, s, o);
    if (lane == 0) red[wid] = s;
    __syncthreads();
    if (t == 0) {
        int tot = 0;
#pragma unroll
        for (int w = 0; w < 8; w++) tot += red[w];
        g_part[b] = tot;
    }
}
// scan3: per-block base via in-smem scan of g_part (scan2 folded in);
// also re-zeroes g_deg for the next call (state invariant across calls).
__global__ void k_scan3(int N) {
    __shared__ int sh[SCHUNK];
    __shared__ int sp[128];
    int b = blockIdx.x, t = threadIdx.x;
    if (t < 128) sp[t] = (t < SBLK) ? g_part[t] : 0;
    __syncthreads();
#pragma unroll
    for (int off = 1; off < 128; off <<= 1) {
        int u = (t < 128 && t >= off) ? sp[t - off] : 0;
        __syncthreads();
        if (t < 128) sp[t] += u;
        __syncthreads();
    }
    const int base = (b == 0) ? 0 : sp[b - 1];

    int i = b * SCHUNK + t;
    int v = 0;
    if (i < N) {
        v = g_deg[i] + 1;
        g_deg[i] = 0;                                    // reset for next call's hist
    }
    sh[t] = v;
    __syncthreads();
    for (int off = 1; off < SCHUNK; off <<= 1) {
        int u = (t >= off) ? sh[t - off] : 0;
        __syncthreads();
        sh[t] += u;
        __syncthreads();
    }
    if (i < N) {
        int excl = base + sh[t] - v;
        g_rowptr[i] = excl;
        g_cursor[i] = excl;
        if (i == N - 1) g_rowptr[N] = base + sh[t];
    }
}
__global__ void k_scatter(const int* __restrict__ src, const int* __restrict__ dst,
                          int E0, int N) {
    int i = blockIdx.x * blockDim.x + threadIdx.x;
    int tot = E0 + N;
    if (i >= tot) return;
    int s, d;
    if (i < E0) { s = src[i]; d = dst[i]; }
    else        { s = d = i - E0; }
    int p = atomicAdd(&g_cursor[d], 1);
    g_csrc[p] = s;
}

// ---------------- mma.sync GEMM: h = x @ W (bf16 hi/lo split), fused attn dots ----------------
// 256 rows per CTA as two sequential 128-row subtiles reusing the smem W image.
__global__ void __launch_bounds__(256, 1) k_gemm(int xsel, int wsel,
        const float* __restrict__ a_s, const float* __restrict__ a_d, int N) {
    extern __shared__ char smem[];
    const uint32_t sb = smem_u32(smem);
    const int tid = threadIdx.x, w = tid >> 5, lane = tid & 31;
    const __half* __restrict__ x = xsel ? g_y : g_x;

    if (tid < 128) {
        *(float*)(smem + OFF_AS + tid * 4) = a_s[tid];
        *(float*)(smem + OFF_AD + tid * 4) = a_d[tid];
    }
    {
        const uint4* wsrc = g_wb[wsel];
        uint4* wdst = (uint4*)(smem + OFF_WHI);
        const int cnt = 2 * TILE_B / 16;          // 4352
#pragma unroll
        for (int i = tid; i < cnt; i += 256)
            wdst[i] = wsrc[i];
    }

    const int arow = (w * 16 + (lane & 15)) * PAD + ((lane >> 4) << 3);
    const int brow = ((lane & 7) + ((lane >> 4) << 3)) * PAD + (((lane >> 3) & 1) << 3);
    const uint32_t abase[3] = { sb + OFF_AHI, sb + OFF_AHI, sb + OFF_ALO };
    const uint32_t wbase[3] = { sb + OFF_WHI, sb + OFF_WLO, sb + OFF_WHI };

#pragma unroll
    for (int t2 = 0; t2 < 2; t2++) {
        const int rb = blockIdx.x * 256 + t2 * 128;
        if (rb >= N) break;                               // uniform across CTA
        __syncthreads();                                  // A smem free (and W copy done on t2=0)

        // load + split-convert fp16 x subtile into A_hi / A_lo (padded row-major)
        for (int i = tid; i < 128 * 64; i += 256) {
            int row = i >> 6;
            int c2  = (i & 63) << 1;
            int gr  = rb + row;
            float v0 = 0.f, v1 = 0.f;
            if (gr < N) {
                const float2 v = __half22float2(*(const __half2*)(x + (size_t)gr * D + c2));
                v0 = v.x; v1 = v.y;
            }
            __nv_bfloat16 h0 = __float2bfloat16(v0), h1 = __float2bfloat16(v1);
            __nv_bfloat16 l0 = __float2bfloat16(v0 - __bfloat162float(h0));
            __nv_bfloat16 l1 = __float2bfloat16(v1 - __bfloat162float(h1));
            __nv_bfloat162 hp, lp;
            hp.x = h0; hp.y = h1; lp.x = l0; lp.y = l1;
            uint32_t off = (uint32_t)(row * PAD + c2) * 2;
            *(uint32_t*)(smem + OFF_AHI + off) = *(uint32_t*)&hp;
            *(uint32_t*)(smem + OFF_ALO + off) = *(uint32_t*)&lp;
        }
        __syncthreads();

        float acc[16][4];
#pragma unroll
        for (int f = 0; f < 16; f++)
#pragma unroll
            for (int j = 0; j < 4; j++) acc[f][j] = 0.f;

#pragma unroll
        for (int p = 0; p < 3; p++) {
            const uint32_t ab = abase[p] + (uint32_t)arow * 2;
            const uint32_t bb = wbase[p] + (uint32_t)brow * 2;
#pragma unroll
            for (int k = 0; k < 8; k++) {
                uint32_t a0, a1, a2, a3;
                ldsm4(a0, a1, a2, a3, ab + (uint32_t)(k * 16) * 2);
#pragma unroll
                for (int f = 0; f < 8; f++) {
                    uint32_t b0, b1, b2, b3;
                    ldsm4(b0, b1, b2, b3, bb + (uint32_t)(f * 16 * PAD + k * 16) * 2);
                    mma16816(acc[2*f][0], acc[2*f][1], acc[2*f][2], acc[2*f][3],
                             a0, a1, a2, a3, b0, b1);
                    mma16816(acc[2*f+1][0], acc[2*f+1][1], acc[2*f+1][2], acc[2*f+1][3],
                             a0, a1, a2, a3, b2, b3);
                }
            }
        }

        const int g = lane >> 2, t = lane & 3;
        const int row0 = rb + w * 16 + g;
        const int row1 = row0 + 8;
        float s0 = 0.f, d0 = 0.f, s1 = 0.f, d1 = 0.f;
#pragma unroll
        for (int f = 0; f < 16; f++) {
            const int cf = f * 8 + 2 * t;
            float2 asv = *(const float2*)(smem + OFF_AS + cf * 4);
            float2 adv = *(const float2*)(smem + OFF_AD + cf * 4);
            s0 += acc[f][0] * asv.x + acc[f][1] * asv.y;
            d0 += acc[f][0] * adv.x + acc[f][1] * adv.y;
            s1 += acc[f][2] * asv.x + acc[f][3] * asv.y;
            d1 += acc[f][2] * adv.x + acc[f][3] * adv.y;
            if (row0 < N)
                *(__half2*)(g_hh + (size_t)row0 * D + cf) = __floats2half2_rn(acc[f][0], acc[f][1]);
            if (row1 < N)
                *(__half2*)(g_hh + (size_t)row1 * D + cf) = __floats2half2_rn(acc[f][2], acc[f][3]);
        }
        for (int o = 1; o <= 2; o <<= 1) {
            s0 += __shfl_xor_sync(0xffffffffu, s0, o);
            d0 += __shfl_xor_sync(0xffffffffu, d0, o);
            s1 += __shfl_xor_sync(0xffffffffu, s1, o);
            d1 += __shfl_xor_sync(0xffffffffu, d1, o);
        }
        if (t == 0) {
            if (row0 < N) { g_as[row0] = s0; g_ad[row0] = d0; }
            if (row1 < N) { g_as[row1] = s1; g_ad[row1] = d1; }
        }
    }
}

// ---------------- per-destination softmax + aggregation ----------------
// No max-subtraction: softmax is shift-invariant and |e| is O(10) here, so
// exp(e) stays comfortably inside fp32 range.
template <bool RELU>
__global__ void k_aggr(const float* __restrict__ b, int outsel, int N) {
    __shared__ float sw[4][CAPW];
    __shared__ int   ss[4][CAPW];
    const int wrp = threadIdx.x >> 5, lane = threadIdx.x & 31;
    const int n = blockIdx.x * 4 + wrp;
    if (n >= N) return;
    const int beg = g_rowptr[n];
    const int end = g_rowptr[n + 1];
    const float adn = g_ad[n];

    // single edge pass: w = exp(leaky(as[src]+ad)); cache w,src; accumulate sum
    float lsum = 0.f;
    for (int j = beg + lane; j < end; j += 32) {
        int s = g_csrc[j];
        float e = g_as[s] + adn;
        e = e > 0.f ? e : 0.2f * e;
        float w = __expf(e);
        lsum += w;
        int idx = j - beg;
        if (idx < CAPW) { sw[wrp][idx] = w; ss[wrp][idx] = s; }
    }
#pragma unroll
    for (int o = 16; o; o >>= 1) lsum += __shfl_xor_sync(0xffffffffu, lsum, o);
    const float inv = 1.f / (lsum + 1e-16f);
    __syncwarp();

    // weighted aggregation of fp16 h rows; lane owns channels [4*lane, 4*lane+4)
    float4 acc = make_float4(0.f, 0.f, 0.f, 0.f);
    const int cnt = min(end - beg, CAPW);
#pragma unroll 4
    for (int j = 0; j < cnt; j++) {
        const float w = sw[wrp][j];
        const uint2 raw = *(const uint2*)(g_hh + (size_t)ss[wrp][j] * D + lane * 4);
        const float2 p0 = __half22float2(*(const __half2*)&raw.x);
        const float2 p1 = __half22float2(*(const __half2*)&raw.y);
        acc.x = fmaf(w, p0.x, acc.x);
        acc.y = fmaf(w, p0.y, acc.y);
        acc.z = fmaf(w, p1.x, acc.z);
        acc.w = fmaf(w, p1.y, acc.w);
    }
    for (int j = beg + CAPW; j < end; j++) {              // essentially-never fallback
        int s = g_csrc[j];
        float e = g_as[s] + adn;
        e = e > 0.f ? e : 0.2f * e;
        float w = __expf(e);
        const uint2 raw = *(const uint2*)(g_hh + (size_t)s * D + lane * 4);
        const float2 p0 = __half22float2(*(const __half2*)&raw.x);
        const float2 p1 = __half22float2(*(const __half2*)&raw.y);
        acc.x = fmaf(w, p0.x, acc.x);
        acc.y = fmaf(w, p0.y, acc.y);
        acc.z = fmaf(w, p1.x, acc.z);
        acc.w = fmaf(w, p1.y, acc.w);
    }
    const float4 bv = *(const float4*)(b + lane * 4);
    acc.x = fmaf(acc.x, inv, bv.x);
    acc.y = fmaf(acc.y, inv, bv.y);
    acc.z = fmaf(acc.z, inv, bv.z);
    acc.w = fmaf(acc.w, inv, bv.w);
    if (RELU) {
        acc.x = fmaxf(acc.x, 0.f); acc.y = fmaxf(acc.y, 0.f);
        acc.z = fmaxf(acc.z, 0.f); acc.w = fmaxf(acc.w, 0.f);
    }
    __half* __restrict__ y = outsel ? g_y : g_x;
    uint2 pk;
    *(__half2*)&pk.x = __floats2half2_rn(acc.x, acc.y);
    *(__half2*)&pk.y = __floats2half2_rn(acc.z, acc.w);
    *(uint2*)(y + (size_t)n * D + lane * 4) = pk;
}

// ---------------- global mean pool (fp16 y -> fp32 out) ----------------
__global__ void k_pool(float* __restrict__ out) {
    int g = blockIdx.x;
    int c = threadIdx.x;
    int beg = g_goff[g], end = g_goff[g + 1];
    float acc = 0.f;
    for (int i = beg; i < end; i++) acc += __half2float(g_y[(size_t)i * D + c]);
    out[g * D + c] = acc / fmaxf((float)(end - beg), 1.f);
}

// ---------------- launch ----------------
extern "C" void kernel_launch(void* const* d_in, const int* in_sizes, int n_in,
                              void* d_out, int out_size) {
    const int*   node_ids = (const int*)d_in[0];
    const int*   ei       = (const int*)d_in[1];
    const int*   batch    = (const int*)d_in[2];
    const float* emb      = (const float*)d_in[3];
    const float* W1  = (const float*)d_in[4];
    const float* as1 = (const float*)d_in[5];
    const float* ad1 = (const float*)d_in[6];
    const float* b1  = (const float*)d_in[7];
    const float* W2  = (const float*)d_in[8];
    const float* as2 = (const float*)d_in[9];
    const float* ad2 = (const float*)d_in[10];
    const float* b2  = (const float*)d_in[11];
    const float* W3  = (const float*)d_in[12];
    const float* as3 = (const float*)d_in[13];
    const float* ad3 = (const float*)d_in[14];
    const float* b3  = (const float*)d_in[15];

    const int N  = in_sizes[0];          // 50000
    const int E0 = in_sizes[1] / 2;      // 800000
    const int* src = ei;
    const int* dst = ei + E0;
    float* out = (float*)d_out;

    const int tot   = E0 + N;
    const int sblk  = (N + SCHUNK - 1) / SCHUNK;
    const int mblk  = (N + 255) / 256;             // 256 rows per CTA
    const int ablk  = (N + 3) / 4;

    cudaFuncSetAttribute(k_gemm, cudaFuncAttributeMaxDynamicSharedMemorySize, GEMM_SMEM);

    // lazy one-time stream/event creation (first call is the uncaptured
    // correctness run; capture replays identical launches + deps each call)
    static cudaStream_t s_csr = nullptr;
    static cudaEvent_t  ev_setup = nullptr, ev_csr = nullptr;
    if (s_csr == nullptr) {
        cudaStreamCreateWithFlags(&s_csr, cudaStreamNonBlocking);
        cudaEventCreateWithFlags(&ev_setup, cudaEventDisableTiming);
        cudaEventCreateWithFlags(&ev_csr, cudaEventDisableTiming);
    }

    // 0: fused setup (embed | hist | prepw x3 | goff) on main stream
    k_setup<<<NB_SETUP, 256>>>(node_ids, (const float4*)emb, batch, dst, E0, W1, W2, W3, N);
    cudaEventRecord(ev_setup, 0);

    // CSR chain forked onto side stream (depends only on setup's hist)
    cudaStreamWaitEvent(s_csr, ev_setup, 0);
    k_scan1<<<sblk, 256, 0, s_csr>>>(N);
    k_scan3<<<sblk, SCHUNK, 0, s_csr>>>(N);
    k_scatter<<<(tot + 255) / 256, 256, 0, s_csr>>>(src, dst, E0, N);
    cudaEventRecord(ev_csr, s_csr);

    // layer-1 GEMM runs concurrently with the CSR chain
    k_gemm<<<mblk, 256, GEMM_SMEM>>>(0, 0, as1, ad1, N);

    // join: aggr needs both gemm1 (main stream order) and CSR (event)
    cudaStreamWaitEvent(0, ev_csr, 0);
    k_aggr<true><<<ablk, 128>>>(b1, 1, N);                   // layer1 out -> g_y
    k_gemm<<<mblk, 256, GEMM_SMEM>>>(1, 1, as2, ad2, N);     // layer2 gemm (x=g_y)
    k_aggr<true><<<ablk, 128>>>(b2, 0, N);                   // layer2 out -> g_x
    k_gemm<<<mblk, 256, GEMM_SMEM>>>(0, 2, as3, ad3, N);     // layer3 gemm (x=g_x)
    k_aggr<false><<<ablk, 128>>>(b3, 1, N);                  // layer3 out -> g_y
    k_pool<<<NG, D>>>(out);
}

// round 17
// speedup vs baseline: 1.1339x; 1.1339x over previous
#include <cuda_runtime.h>
#include <cuda_bf16.h>
#include <cuda_fp16.h>
#include <cstdint>

#define D      128
#define MAXN   50000
#define MAXE   850000
#define NG     512
#define SCHUNK 512
#define SBLK   ((MAXN + SCHUNK - 1) / SCHUNK)   // 98
#define TILE_M 128
#define PAD    136                               // smem row stride in bf16 elems
#define CAPW   64                                // per-warp edge cache

// ---- dynamic smem layout for MMA GEMM (bytes) ----
#define OFF_AS   0
#define OFF_AD   512
#define OFF_AHI  1024
#define TILE_B   (128 * PAD * 2)                 // 34816
#define OFF_ALO  (OFF_AHI + TILE_B)
#define OFF_WHI  (OFF_ALO + TILE_B)
#define OFF_WLO  (OFF_WHI + TILE_B)
#define GEMM_SMEM (OFF_WLO + TILE_B)             // 140288 bytes

// ---- fused setup job split (blocks of 256 threads) ----
#define NB_EMBED ((MAXN * (D / 4) + 255) / 256)  // 6250
#define NB_HIST  ((MAXE + 255) / 256)            // 3321 (covers any E0 <= MAXE)
#define NB_PREPW ((128 * 64 + 255) / 256)        // 32
#define NB_GOFF  3                               // 768 threads >= NG+1 = 513 entries
#define NB_SETUP (NB_EMBED + NB_HIST + 3 * NB_PREPW + NB_GOFF)

// ---------------- scratch (device globals; no allocation) ----------------
__device__ __half g_x[MAXN * D];                 // fp16 activations (layer inputs)
__device__ __half g_y[MAXN * D];
__device__ __half g_hh[MAXN * D];                // h in fp16 for the edge gather
__device__ float  g_as[MAXN];
__device__ float  g_ad[MAXN];
__device__ int    g_deg[MAXN];                   // zeroed at load; re-zeroed by k_scan3
__device__ int    g_rowptr[MAXN + 1];
__device__ int    g_cursor[MAXN];
__device__ int    g_csrc[MAXE];
__device__ int    g_goff[NG + 1];
__device__ int    g_part[SBLK];
// per-layer W images: [n][k] bf16, padded stride PAD, hi then lo (34816 B each)
__device__ uint4  g_wb[3][2 * TILE_B / 16];

// ---------------- PTX helpers ----------------
__device__ __forceinline__ uint32_t smem_u32(const void* p) {
    uint32_t a;
    asm("{ .reg .u64 t; cvta.to.shared.u64 t, %1; cvt.u32.u64 %0, t; }" : "=r"(a) : "l"(p));
    return a;
}
__device__ __forceinline__ void ldsm4(uint32_t& r0, uint32_t& r1, uint32_t& r2, uint32_t& r3,
                                      uint32_t addr) {
    asm volatile("ldmatrix.sync.aligned.m8n8.x4.shared.b16 {%0,%1,%2,%3}, [%4];"
                 : "=r"(r0), "=r"(r1), "=r"(r2), "=r"(r3) : "r"(addr));
}
__device__ __forceinline__ void mma16816(float& c0, float& c1, float& c2, float& c3,
                                         uint32_t a0, uint32_t a1, uint32_t a2, uint32_t a3,
                                         uint32_t b0, uint32_t b1) {
    asm volatile(
        "mma.sync.aligned.m16n8k16.row.col.f32.bf16.bf16.f32 "
        "{%0,%1,%2,%3}, {%4,%5,%6,%7}, {%8,%9}, {%0,%1,%2,%3};"
        : "+f"(c0), "+f"(c1), "+f"(c2), "+f"(c3)
        : "r"(a0), "r"(a1), "r"(a2), "r"(a3), "r"(b0), "r"(b1));
}

// ---------------- fused setup: embed | hist | prepw x3 | goff ----------------
__device__ __forceinline__ void do_prepw(int w, const float* __restrict__ W, int i) {
    if (i >= 128 * 64) return;
    int n  = i >> 6;
    int k2 = (i & 63) << 1;
    float v0 = W[k2 * D + n];
    float v1 = W[(k2 + 1) * D + n];
    __nv_bfloat16 h0 = __float2bfloat16(v0), h1 = __float2bfloat16(v1);
    __nv_bfloat16 l0 = __float2bfloat16(v0 - __bfloat162float(h0));
    __nv_bfloat16 l1 = __float2bfloat16(v1 - __bfloat162float(h1));
    __nv_bfloat162 hp, lp;
    hp.x = h0; hp.y = h1; lp.x = l0; lp.y = l1;
    char* base = (char*)g_wb[w];
    uint32_t off = (uint32_t)(n * PAD + k2) * 2;
    *(uint32_t*)(base + off)          = *(uint32_t*)&hp;
    *(uint32_t*)(base + TILE_B + off) = *(uint32_t*)&lp;
}

__global__ void k_setup(const int* __restrict__ ids, const float4* __restrict__ emb,
                        const int* __restrict__ batch, const int* __restrict__ dst, int E0,
                        const float* __restrict__ W1, const float* __restrict__ W2,
                        const float* __restrict__ W3, int N) {
    const int b = blockIdx.x, t = threadIdx.x;
    if (b < NB_EMBED) {                                   // embedding gather -> fp16 x
        int i = b * 256 + t;
        if (i < N * (D / 4)) {
            int node = i >> 5;
            int c    = i & 31;
            float4 v = emb[ids[node] * (D / 4) + c];
            uint2 pk;
            *(__half2*)&pk.x = __floats2half2_rn(v.x, v.y);
            *(__half2*)&pk.y = __floats2half2_rn(v.z, v.w);
            ((uint2*)g_x)[i] = pk;
        }
        return;
    }
    int b1 = b - NB_EMBED;
    if (b1 < NB_HIST) {                                   // degree histogram (deg starts 0)
        int i = b1 * 256 + t;
        if (i < E0) atomicAdd(&g_deg[dst[i]], 1);
        return;
    }
    b1 -= NB_HIST;
    if (b1 < 3 * NB_PREPW) {                              // W split/pack
        int w = b1 / NB_PREPW;
        int i = (b1 - w * NB_PREPW) * 256 + t;
        do_prepw(w, w == 0 ? W1 : (w == 1 ? W2 : W3), i);
        return;
    }
    b1 -= 3 * NB_PREPW;
    {                                                     // goff: lower_bound(batch, g), g in [0, NG]
        int g = b1 * 256 + t;
        if (g > NG) return;
        int lo = 0, hi = N;
        while (lo < hi) {
            int mid = (lo + hi) >> 1;
            if (batch[mid] < g) lo = mid + 1; else hi = mid;
        }
        g_goff[g] = lo;
    }
}

// ---------------- CSR scan (deg+1 accounts for the self-loop) ----------------
__global__ void k_scan1(int N) {
    __shared__ int red[8];
    int b = blockIdx.x, t = threadIdx.x;
    int base = b * SCHUNK;
    int s = 0;
    int i0 = base + t, i1 = base + t + 256;
    if (i0 < N) s += g_deg[i0] + 1;
    if (i1 < N) s += g_deg[i1] + 1;
    int lane = t & 31, wid = t >> 5;
    for (int o = 16; o; o >>= 1) s += __shfl_xor_sync(0xffffffffu, s, o);
    if (lane == 0) red[wid] = s;
    __syncthreads();
    if (t == 0) {
        int tot = 0;
#pragma unroll
        for (int w = 0; w < 8; w++) tot += red[w];
        g_part[b] = tot;
    }
}
// scan3: per-block base via in-smem scan of g_part (scan2 folded in);
// also re-zeroes g_deg for the next call (state invariant across calls).
__global__ void k_scan3(int N) {
    __shared__ int sh[SCHUNK];
    __shared__ int sp[128];
    int b = blockIdx.x, t = threadIdx.x;
    if (t < 128) sp[t] = (t < SBLK) ? g_part[t] : 0;
    __syncthreads();
#pragma unroll
    for (int off = 1; off < 128; off <<= 1) {
        int u = (t < 128 && t >= off) ? sp[t - off] : 0;
        __syncthreads();
        if (t < 128) sp[t] += u;
        __syncthreads();
    }
    const int base = (b == 0) ? 0 : sp[b - 1];

    int i = b * SCHUNK + t;
    int v = 0;
    if (i < N) {
        v = g_deg[i] + 1;
        g_deg[i] = 0;                                    // reset for next call's hist
    }
    sh[t] = v;
    __syncthreads();
    for (int off = 1; off < SCHUNK; off <<= 1) {
        int u = (t >= off) ? sh[t - off] : 0;
        __syncthreads();
        sh[t] += u;
        __syncthreads();
    }
    if (i < N) {
        int excl = base + sh[t] - v;
        g_rowptr[i] = excl;
        g_cursor[i] = excl;
        if (i == N - 1) g_rowptr[N] = base + sh[t];
    }
}
__global__ void k_scatter(const int* __restrict__ src, const int* __restrict__ dst,
                          int E0, int N) {
    int i = blockIdx.x * blockDim.x + threadIdx.x;
    int tot = E0 + N;
    if (i >= tot) return;
    int s, d;
    if (i < E0) { s = src[i]; d = dst[i]; }
    else        { s = d = i - E0; }
    int p = atomicAdd(&g_cursor[d], 1);
    g_csrc[p] = s;
}

// ---------------- mma.sync GEMM: h = x @ W (bf16 hi/lo split), fused attn dots ----------------
// One 128-row tile per CTA (R15 structure; fp16 x input).
__global__ void __launch_bounds__(256, 1) k_gemm(int xsel, int wsel,
        const float* __restrict__ a_s, const float* __restrict__ a_d, int N) {
    extern __shared__ char smem[];
    const uint32_t sb = smem_u32(smem);
    const int tid = threadIdx.x, w = tid >> 5, lane = tid & 31;
    const int rb = blockIdx.x * TILE_M;
    const __half* __restrict__ x = xsel ? g_y : g_x;

    if (tid < 128) {
        *(float*)(smem + OFF_AS + tid * 4) = a_s[tid];
        *(float*)(smem + OFF_AD + tid * 4) = a_d[tid];
    }
    {
        const uint4* wsrc = g_wb[wsel];
        uint4* wdst = (uint4*)(smem + OFF_WHI);
        const int cnt = 2 * TILE_B / 16;          // 4352
#pragma unroll
        for (int i = tid; i < cnt; i += 256)
            wdst[i] = wsrc[i];
    }
    // load + split-convert fp16 x tile into A_hi / A_lo (padded row-major)
    for (int i = tid; i < TILE_M * 64; i += 256) {
        int row = i >> 6;
        int c2  = (i & 63) << 1;
        int gr  = rb + row;
        float v0 = 0.f, v1 = 0.f;
        if (gr < N) {
            const float2 v = __half22float2(*(const __half2*)(x + (size_t)gr * D + c2));
            v0 = v.x; v1 = v.y;
        }
        __nv_bfloat16 h0 = __float2bfloat16(v0), h1 = __float2bfloat16(v1);
        __nv_bfloat16 l0 = __float2bfloat16(v0 - __bfloat162float(h0));
        __nv_bfloat16 l1 = __float2bfloat16(v1 - __bfloat162float(h1));
        __nv_bfloat162 hp, lp;
        hp.x = h0; hp.y = h1; lp.x = l0; lp.y = l1;
        uint32_t off = (uint32_t)(row * PAD + c2) * 2;
        *(uint32_t*)(smem + OFF_AHI + off) = *(uint32_t*)&hp;
        *(uint32_t*)(smem + OFF_ALO + off) = *(uint32_t*)&lp;
    }
    __syncthreads();

    float acc[16][4];
#pragma unroll
    for (int f = 0; f < 16; f++)
#pragma unroll
        for (int j = 0; j < 4; j++) acc[f][j] = 0.f;

    const int arow = (w * 16 + (lane & 15)) * PAD + ((lane >> 4) << 3);
    const int brow = ((lane & 7) + ((lane >> 4) << 3)) * PAD + (((lane >> 3) & 1) << 3);

    const uint32_t abase[3] = { sb + OFF_AHI, sb + OFF_AHI, sb + OFF_ALO };
    const uint32_t wbase[3] = { sb + OFF_WHI, sb + OFF_WLO, sb + OFF_WHI };

#pragma unroll
    for (int p = 0; p < 3; p++) {
        const uint32_t ab = abase[p] + (uint32_t)arow * 2;
        const uint32_t bb = wbase[p] + (uint32_t)brow * 2;
#pragma unroll
        for (int k = 0; k < 8; k++) {
            uint32_t a0, a1, a2, a3;
            ldsm4(a0, a1, a2, a3, ab + (uint32_t)(k * 16) * 2);
#pragma unroll
            for (int f = 0; f < 8; f++) {
                uint32_t b0, b1, b2, b3;
                ldsm4(b0, b1, b2, b3, bb + (uint32_t)(f * 16 * PAD + k * 16) * 2);
                mma16816(acc[2*f][0], acc[2*f][1], acc[2*f][2], acc[2*f][3],
                         a0, a1, a2, a3, b0, b1);
                mma16816(acc[2*f+1][0], acc[2*f+1][1], acc[2*f+1][2], acc[2*f+1][3],
                         a0, a1, a2, a3, b2, b3);
            }
        }
    }

    const int g = lane >> 2, t = lane & 3;
    const int row0 = rb + w * 16 + g;
    const int row1 = row0 + 8;
    float s0 = 0.f, d0 = 0.f, s1 = 0.f, d1 = 0.f;
#pragma unroll
    for (int f = 0; f < 16; f++) {
        const int cf = f * 8 + 2 * t;
        float2 asv = *(const float2*)(smem + OFF_AS + cf * 4);
        float2 adv = *(const float2*)(smem + OFF_AD + cf * 4);
        s0 += acc[f][0] * asv.x + acc[f][1] * asv.y;
        d0 += acc[f][0] * adv.x + acc[f][1] * adv.y;
        s1 += acc[f][2] * asv.x + acc[f][3] * asv.y;
        d1 += acc[f][2] * adv.x + acc[f][3] * adv.y;
        if (row0 < N)
            *(__half2*)(g_hh + (size_t)row0 * D + cf) = __floats2half2_rn(acc[f][0], acc[f][1]);
        if (row1 < N)
            *(__half2*)(g_hh + (size_t)row1 * D + cf) = __floats2half2_rn(acc[f][2], acc[f][3]);
    }
    for (int o = 1; o <= 2; o <<= 1) {
        s0 += __shfl_xor_sync(0xffffffffu, s0, o);
        d0 += __shfl_xor_sync(0xffffffffu, d0, o);
        s1 += __shfl_xor_sync(0xffffffffu, s1, o);
        d1 += __shfl_xor_sync(0xffffffffu, d1, o);
    }
    if (t == 0) {
        if (row0 < N) { g_as[row0] = s0; g_ad[row0] = d0; }
        if (row1 < N) { g_as[row1] = s1; g_ad[row1] = d1; }
    }
}

// ---------------- per-destination softmax + aggregation ----------------
// No max-subtraction: softmax is shift-invariant and |e| is O(10) here, so
// exp(e) stays comfortably inside fp32 range.
template <bool RELU>
__global__ void k_aggr(const float* __restrict__ b, int outsel, int N) {
    __shared__ float sw[4][CAPW];
    __shared__ int   ss[4][CAPW];
    const int wrp = threadIdx.x >> 5, lane = threadIdx.x & 31;
    const int n = blockIdx.x * 4 + wrp;
    if (n >= N) return;
    const int beg = g_rowptr[n];
    const int end = g_rowptr[n + 1];
    const float adn = g_ad[n];

    // single edge pass: w = exp(leaky(as[src]+ad)); cache w,src; accumulate sum
    float lsum = 0.f;
    for (int j = beg + lane; j < end; j += 32) {
        int s = g_csrc[j];
        float e = g_as[s] + adn;
        e = e > 0.f ? e : 0.2f * e;
        float w = __expf(e);
        lsum += w;
        int idx = j - beg;
        if (idx < CAPW) { sw[wrp][idx] = w; ss[wrp][idx] = s; }
    }
#pragma unroll
    for (int o = 16; o; o >>= 1) lsum += __shfl_xor_sync(0xffffffffu, lsum, o);
    const float inv = 1.f / (lsum + 1e-16f);
    __syncwarp();

    // weighted aggregation of fp16 h rows; lane owns channels [4*lane, 4*lane+4)
    float4 acc = make_float4(0.f, 0.f, 0.f, 0.f);
    const int cnt = min(end - beg, CAPW);
#pragma unroll 4
    for (int j = 0; j < cnt; j++) {
        const float w = sw[wrp][j];
        const uint2 raw = *(const uint2*)(g_hh + (size_t)ss[wrp][j] * D + lane * 4);
        const float2 p0 = __half22float2(*(const __half2*)&raw.x);
        const float2 p1 = __half22float2(*(const __half2*)&raw.y);
        acc.x = fmaf(w, p0.x, acc.x);
        acc.y = fmaf(w, p0.y, acc.y);
        acc.z = fmaf(w, p1.x, acc.z);
        acc.w = fmaf(w, p1.y, acc.w);
    }
    for (int j = beg + CAPW; j < end; j++) {              // essentially-never fallback
        int s = g_csrc[j];
        float e = g_as[s] + adn;
        e = e > 0.f ? e : 0.2f * e;
        float w = __expf(e);
        const uint2 raw = *(const uint2*)(g_hh + (size_t)s * D + lane * 4);
        const float2 p0 = __half22float2(*(const __half2*)&raw.x);
        const float2 p1 = __half22float2(*(const __half2*)&raw.y);
        acc.x = fmaf(w, p0.x, acc.x);
        acc.y = fmaf(w, p0.y, acc.y);
        acc.z = fmaf(w, p1.x, acc.z);
        acc.w = fmaf(w, p1.y, acc.w);
    }
    const float4 bv = *(const float4*)(b + lane * 4);
    acc.x = fmaf(acc.x, inv, bv.x);
    acc.y = fmaf(acc.y, inv, bv.y);
    acc.z = fmaf(acc.z, inv, bv.z);
    acc.w = fmaf(acc.w, inv, bv.w);
    if (RELU) {
        acc.x = fmaxf(acc.x, 0.f); acc.y = fmaxf(acc.y, 0.f);
        acc.z = fmaxf(acc.z, 0.f); acc.w = fmaxf(acc.w, 0.f);
    }
    __half* __restrict__ y = outsel ? g_y : g_x;
    uint2 pk;
    *(__half2*)&pk.x = __floats2half2_rn(acc.x, acc.y);
    *(__half2*)&pk.y = __floats2half2_rn(acc.z, acc.w);
    *(uint2*)(y + (size_t)n * D + lane * 4) = pk;
}

// ---------------- global mean pool (fp16 y -> fp32 out) ----------------
__global__ void k_pool(float* __restrict__ out) {
    int g = blockIdx.x;
    int c = threadIdx.x;
    int beg = g_goff[g], end = g_goff[g + 1];
    float acc = 0.f;
    for (int i = beg; i < end; i++) acc += __half2float(g_y[(size_t)i * D + c]);
    out[g * D + c] = acc / fmaxf((float)(end - beg), 1.f);
}

// ---------------- launch ----------------
extern "C" void kernel_launch(void* const* d_in, const int* in_sizes, int n_in,
                              void* d_out, int out_size) {
    const int*   node_ids = (const int*)d_in[0];
    const int*   ei       = (const int*)d_in[1];
    const int*   batch    = (const int*)d_in[2];
    const float* emb      = (const float*)d_in[3];
    const float* W1  = (const float*)d_in[4];
    const float* as1 = (const float*)d_in[5];
    const float* ad1 = (const float*)d_in[6];
    const float* b1  = (const float*)d_in[7];
    const float* W2  = (const float*)d_in[8];
    const float* as2 = (const float*)d_in[9];
    const float* ad2 = (const float*)d_in[10];
    const float* b2  = (const float*)d_in[11];
    const float* W3  = (const float*)d_in[12];
    const float* as3 = (const float*)d_in[13];
    const float* ad3 = (const float*)d_in[14];
    const float* b3  = (const float*)d_in[15];

    const int N  = in_sizes[0];          // 50000
    const int E0 = in_sizes[1] / 2;      // 800000
    const int* src = ei;
    const int* dst = ei + E0;
    float* out = (float*)d_out;

    const int tot   = E0 + N;
    const int sblk  = (N + SCHUNK - 1) / SCHUNK;
    const int mblk  = (N + TILE_M - 1) / TILE_M;   // 128 rows per CTA (reverted)
    const int ablk  = (N + 3) / 4;

    cudaFuncSetAttribute(k_gemm, cudaFuncAttributeMaxDynamicSharedMemorySize, GEMM_SMEM);

    // lazy one-time stream/event creation (first call is the uncaptured
    // correctness run; capture replays identical launches + deps each call)
    static cudaStream_t s_csr = nullptr;
    static cudaEvent_t  ev_setup = nullptr, ev_csr = nullptr;
    if (s_csr == nullptr) {
        cudaStreamCreateWithFlags(&s_csr, cudaStreamNonBlocking);
        cudaEventCreateWithFlags(&ev_setup, cudaEventDisableTiming);
        cudaEventCreateWithFlags(&ev_csr, cudaEventDisableTiming);
    }

    // 0: fused setup (embed | hist | prepw x3 | goff) on main stream
    k_setup<<<NB_SETUP, 256>>>(node_ids, (const float4*)emb, batch, dst, E0, W1, W2, W3, N);
    cudaEventRecord(ev_setup, 0);

    // CSR chain forked onto side stream (depends only on setup's hist)
    cudaStreamWaitEvent(s_csr, ev_setup, 0);
    k_scan1<<<sblk, 256, 0, s_csr>>>(N);
    k_scan3<<<sblk, SCHUNK, 0, s_csr>>>(N);
    k_scatter<<<(tot + 255) / 256, 256, 0, s_csr>>>(src, dst, E0, N);
    cudaEventRecord(ev_csr, s_csr);

    // layer-1 GEMM runs concurrently with the CSR chain
    k_gemm<<<mblk, 256, GEMM_SMEM>>>(0, 0, as1, ad1, N);

    // join: aggr needs both gemm1 (main stream order) and CSR (event)
    cudaStreamWaitEvent(0, ev_csr, 0);
    k_aggr<true><<<ablk, 128>>>(b1, 1, N);                   // layer1 out -> g_y
    k_gemm<<<mblk, 256, GEMM_SMEM>>>(1, 1, as2, ad2, N);     // layer2 gemm (x=g_y)
    k_aggr<true><<<ablk, 128>>>(b2, 0, N);                   // layer2 out -> g_x
    k_gemm<<<mblk, 256, GEMM_SMEM>>>(0, 2, as3, ad3, N);     // layer3 gemm (x=g_x)
    k_aggr<false><<<ablk, 128>>>(b3, 1, N);                  // layer3 out -> g_y
    k_pool<<<NG, D>>>(out);
}